// round 8
// baseline (speedup 1.0000x reference)
#include <cuda_runtime.h>

#define NN 100000
#define EE 3200000
#define GG 512
#define HH 30
#define HP 32          // padded row stride (128 bytes)
#define FIN 10

// ---- static scratch (no runtime allocation) ----
__device__ __align__(128) float d_T[NN * HP];   // h @ W (padded rows)
__device__ __align__(128) float d_A[NN * HP];   // aggregated output
__device__ float d_dis[NN];          // 1/sqrt(deg)
__device__ int   d_cnt[NN];          // in-degree count
__device__ int   d_off[NN + 1];      // CSR offsets (by destination)
__device__ int   d_fill[NN];         // position-claim counters
__device__ int   d_er[EE];           // CSR: src per slot
__device__ float d_ew[EE];           // CSR: raw weight per slot
__device__ float d_en[EE];           // CSR: dis[src]*w per slot
__device__ int   d_seglo[GG + 1];    // graph segment bounds in sorted batch
__device__ float d_pooled[GG * HP];  // pooled features

__global__ void k_init() {
    int i = blockIdx.x * blockDim.x + threadIdx.x;
    if (i < NN) d_cnt[i] = 0;
}

// Count in-degree. edge_index is INT32 (JAX x64 disabled downcasts int64).
__global__ void k_cnt(const int* __restrict__ ei) {
    int e = blockIdx.x * blockDim.x + threadIdx.x;
    if (e >= EE) return;
    atomicAdd(&d_cnt[ei[EE + e]], 1);     // col = destination
}

// Single-block exclusive scan of d_cnt -> d_off / d_fill. 512 threads, chunk 196.
__global__ void k_scan() {
    __shared__ int s[512];
    const int CH = 196;                  // 512*196 = 100352 >= NN
    int t = threadIdx.x;
    int base = t * CH;
    int sum = 0;
    for (int k = 0; k < CH; k++) {
        int i = base + k;
        if (i < NN) sum += d_cnt[i];
    }
    s[t] = sum;
    __syncthreads();
    for (int off = 1; off < 512; off <<= 1) {
        int v = (t >= off) ? s[t - off] : 0;
        __syncthreads();
        s[t] += v;
        __syncthreads();
    }
    int run = s[t] - sum;                // exclusive prefix
    for (int k = 0; k < CH; k++) {
        int i = base + k;
        if (i < NN) {
            d_off[i] = run;
            d_fill[i] = run;
            run += d_cnt[i];
        }
    }
    if (t == 511) d_off[NN] = run;       // == EE
}

// Scatter edges into CSR slots (int atomicAdd position claim).
__global__ void k_build(const int* __restrict__ ei, const float* __restrict__ w) {
    int e = blockIdx.x * blockDim.x + threadIdx.x;
    if (e >= EE) return;
    int r = ei[e];
    int c = ei[EE + e];
    int pos = atomicAdd(&d_fill[c], 1);
    d_er[pos] = r;
    d_ew[pos] = w[e];
}

// Per-node weighted degree from CSR (self-loop weight 1) -> dis. No atomics.
__global__ void k_degdis() {
    int i = blockIdx.x * blockDim.x + threadIdx.x;
    if (i >= NN) return;
    int s = d_off[i], e = d_off[i + 1];
    float deg = 1.0f;                    // self-loop
    for (int j = s; j < e; j++) deg += d_ew[j];
    d_dis[i] = rsqrtf(deg);              // deg >= 1 always
}

// Per-slot coefficient: dis[src] * w.  (dis[dst] hoists out of the sum.)
__global__ void k_norm() {
    int j = blockIdx.x * blockDim.x + threadIdx.x;
    if (j >= EE) return;
    d_en[j] = d_ew[j] * d_dis[d_er[j]];
}

// Layer 1: T = x @ W1 (padded cols zeroed)
__global__ void k_mm1(const float* __restrict__ x, const float* __restrict__ W1) {
    __shared__ float sW[FIN * HH];
    for (int t = threadIdx.x; t < FIN * HH; t += blockDim.x) sW[t] = W1[t];
    __syncthreads();
    int i = blockIdx.x * blockDim.x + threadIdx.x;
    if (i >= NN) return;
    float xv[FIN];
#pragma unroll
    for (int k = 0; k < FIN; k++) xv[k] = x[i * FIN + k];
#pragma unroll
    for (int j = 0; j < HH; j++) {
        float t = 0.0f;
#pragma unroll
        for (int k = 0; k < FIN; k++) t += xv[k] * sW[k * HH + j];
        d_T[i * HP + j] = t;
    }
    d_T[i * HP + 30] = 0.0f;
    d_T[i * HP + 31] = 0.0f;
}

// Layers 2/3: h = relu(A + b_prev); T = h @ W
__global__ void k_mm23(const float* __restrict__ W, const float* __restrict__ bprev) {
    __shared__ float sW[HH * HH];
    __shared__ float sb[HH];
    for (int t = threadIdx.x; t < HH * HH; t += blockDim.x) sW[t] = W[t];
    if (threadIdx.x < HH) sb[threadIdx.x] = bprev[threadIdx.x];
    __syncthreads();
    int i = blockIdx.x * blockDim.x + threadIdx.x;
    if (i >= NN) return;
    float h[HH];
#pragma unroll
    for (int k = 0; k < HH; k++) h[k] = fmaxf(d_A[i * HP + k] + sb[k], 0.0f);
#pragma unroll
    for (int j = 0; j < HH; j++) {
        float t = 0.0f;
#pragma unroll
        for (int k = 0; k < HH; k++) t += h[k] * sW[k * HH + j];
        d_T[i * HP + j] = t;
    }
    d_T[i * HP + 30] = 0.0f;
    d_T[i * HP + 31] = 0.0f;
}

// Gather: one warp per node, lane = feature column (padding lanes read zeros).
// A[i] = dis[i] * ( sum_j en[j]*T[er[j]] + dis[i]*T[i] ).  No atomics; scalar
// coalesced LDG only (each edge = one 128B line). 2-way ILP on the edge loop.
__global__ void k_gather() {
    int warp = (blockIdx.x * blockDim.x + threadIdx.x) >> 5;
    if (warp >= NN) return;
    int lane = threadIdx.x & 31;
    int s = d_off[warp], e = d_off[warp + 1];
    float a0 = 0.0f, a1 = 0.0f;
    int j = s;
    for (; j + 1 < e; j += 2) {
        int   r0 = d_er[j];     float c0 = d_en[j];
        int   r1 = d_er[j + 1]; float c1 = d_en[j + 1];
        a0 += c0 * d_T[r0 * HP + lane];
        a1 += c1 * d_T[r1 * HP + lane];
    }
    if (j < e) a0 += d_en[j] * d_T[d_er[j] * HP + lane];
    float di = d_dis[warp];
    d_A[warp * HP + lane] = di * (a0 + a1 + di * d_T[warp * HP + lane]);
}

// Graph segment boundaries: batch is sorted int32; lower_bound(g).
__global__ void k_bounds(const int* __restrict__ batch) {
    int g = threadIdx.x;                 // 0..511
    int lo = 0, hi = NN;
    while (lo < hi) {
        int mid = (lo + hi) >> 1;
        if (batch[mid] < g) lo = mid + 1; else hi = mid;
    }
    d_seglo[g] = lo;
    if (g == 0) d_seglo[GG] = NN;
}

// Pool: block per graph (8 warps), lane = feature; max over relu(A + b3).
// relu identity 0 == relu of the max (monotone), valid for non-empty segments.
__global__ void k_pool(const float* __restrict__ b3) {
    __shared__ float sm[8][32];
    int g = blockIdx.x;
    int lo = d_seglo[g], hi = d_seglo[g + 1];
    int w = threadIdx.x >> 5, lane = threadIdx.x & 31;
    float bb = (lane < HH) ? b3[lane] : 0.0f;
    float mx = 0.0f;
    for (int i = lo + w; i < hi; i += 8)
        mx = fmaxf(mx, d_A[i * HP + lane] + bb);
    sm[w][lane] = mx;
    __syncthreads();
    if (threadIdx.x < 32) {
        float m = sm[0][lane];
#pragma unroll
        for (int ww = 1; ww < 8; ww++) m = fmaxf(m, sm[ww][lane]);
        d_pooled[g * HP + lane] = m;
    }
}

// Final MLP: out[g] = relu(p @ LW1 + Lb1) @ LW2 + Lb2
__global__ void k_mlp(const float* __restrict__ LW1, const float* __restrict__ Lb1,
                      const float* __restrict__ LW2, const float* __restrict__ Lb2,
                      float* __restrict__ out) {
    __shared__ float sW1[HH * 10];
    __shared__ float sb1[10];
    __shared__ float sW2[10 * 2];
    __shared__ float sb2[2];
    for (int t = threadIdx.x; t < HH * 10; t += blockDim.x) sW1[t] = LW1[t];
    if (threadIdx.x < 10) sb1[threadIdx.x] = Lb1[threadIdx.x];
    if (threadIdx.x < 20) sW2[threadIdx.x] = LW2[threadIdx.x];
    if (threadIdx.x < 2)  sb2[threadIdx.x] = Lb2[threadIdx.x];
    __syncthreads();
    int g = threadIdx.x;
    if (g >= GG) return;
    float p[HH];
#pragma unroll
    for (int k = 0; k < HH; k++) p[k] = d_pooled[g * HP + k];
    float z[10];
#pragma unroll
    for (int j = 0; j < 10; j++) {
        float t = sb1[j];
#pragma unroll
        for (int k = 0; k < HH; k++) t += p[k] * sW1[k * 10 + j];
        z[j] = fmaxf(t, 0.0f);
    }
#pragma unroll
    for (int o = 0; o < 2; o++) {
        float t = sb2[o];
#pragma unroll
        for (int j = 0; j < 10; j++) t += z[j] * sW2[j * 2 + o];
        out[g * 2 + o] = t;
    }
}

extern "C" void kernel_launch(void* const* d_in, const int* in_sizes, int n_in,
                              void* d_out, int out_size) {
    const float* x     = (const float*)d_in[0];
    const int*   ei    = (const int*)d_in[1];    // int32! (JAX x64 disabled)
    const int*   batch = (const int*)d_in[2];    // int32!
    const float* w     = (const float*)d_in[3];
    const float* W1    = (const float*)d_in[4];
    const float* b1    = (const float*)d_in[5];
    const float* W2    = (const float*)d_in[6];
    const float* b2    = (const float*)d_in[7];
    const float* W3    = (const float*)d_in[8];
    const float* b3    = (const float*)d_in[9];
    const float* LW1   = (const float*)d_in[10];
    const float* Lb1   = (const float*)d_in[11];
    const float* LW2   = (const float*)d_in[12];
    const float* Lb2   = (const float*)d_in[13];
    float* out = (float*)d_out;

    const int TB = 256;
    const int gN = (NN + TB - 1) / TB;
    const int gE = (EE + TB - 1) / TB;
    const int gW = (NN * 32) / TB;       // one warp per node (exact multiple)

    k_init<<<gN, TB>>>();
    k_cnt<<<gE, TB>>>(ei);
    k_scan<<<1, 512>>>();
    k_build<<<gE, TB>>>(ei, w);
    k_degdis<<<gN, TB>>>();
    k_norm<<<gE, TB>>>();

    k_mm1<<<gN, TB>>>(x, W1);
    k_gather<<<gW, TB>>>();

    k_mm23<<<gN, TB>>>(W2, b1);
    k_gather<<<gW, TB>>>();

    k_mm23<<<gN, TB>>>(W3, b2);
    k_gather<<<gW, TB>>>();

    k_bounds<<<1, 512>>>(batch);
    k_pool<<<GG, TB>>>(b3);
    k_mlp<<<1, 512>>>(LW1, Lb1, LW2, Lb2, out);
}

// round 10
// speedup vs baseline: 1.0149x; 1.0149x over previous
#include <cuda_runtime.h>

#define NN 100000
#define EE 3200000
#define GG 512
#define HH 30
#define HP 32          // padded row stride (128 bytes)
#define FIN 10

// ---- static scratch (no runtime allocation) ----
__device__ __align__(128) float d_T[NN * HP];   // h @ W (padded rows)
__device__ __align__(128) float d_A[NN * HP];   // aggregated output
__device__ float d_degf[NN];         // weighted degree accumulator
__device__ float d_dis[NN];          // 1/sqrt(deg)
__device__ int   d_cnt[NN];          // in-degree count
__device__ int   d_off[NN + 1];      // CSR offsets (by destination)
__device__ int   d_fill[NN];         // position-claim counters
__device__ int2  d_edge[EE];         // CSR slot: {src, float_bits(dis[src]*w)}
__device__ int   d_seglo[GG + 1];    // graph segment bounds in sorted batch
__device__ float d_pooled[GG * HP];  // pooled features

__global__ void k_init() {
    int i = blockIdx.x * blockDim.x + threadIdx.x;
    if (i < NN) { d_cnt[i] = 0; d_degf[i] = 1.0f; }  // self-loop weight 1
}

// Count in-degree AND accumulate weighted degree (edge_index is int32).
__global__ void k_cnt(const int* __restrict__ ei, const float* __restrict__ w) {
    int e = blockIdx.x * blockDim.x + threadIdx.x;
    if (e >= EE) return;
    int c = ei[EE + e];                  // destination
    atomicAdd(&d_cnt[c], 1);
    atomicAdd(&d_degf[c], w[e]);
}

// Single-block exclusive scan of d_cnt -> d_off / d_fill. 512 threads, chunk 196.
__global__ void k_scan() {
    __shared__ int s[512];
    const int CH = 196;                  // 512*196 = 100352 >= NN
    int t = threadIdx.x;
    int base = t * CH;
    int sum = 0;
    for (int k = 0; k < CH; k++) {
        int i = base + k;
        if (i < NN) sum += d_cnt[i];
    }
    s[t] = sum;
    __syncthreads();
    for (int off = 1; off < 512; off <<= 1) {
        int v = (t >= off) ? s[t - off] : 0;
        __syncthreads();
        s[t] += v;
        __syncthreads();
    }
    int run = s[t] - sum;                // exclusive prefix
    for (int k = 0; k < CH; k++) {
        int i = base + k;
        if (i < NN) {
            d_off[i] = run;
            d_fill[i] = run;
            run += d_cnt[i];
        }
    }
    if (t == 511) d_off[NN] = run;       // == EE
}

__global__ void k_dis() {
    int i = blockIdx.x * blockDim.x + threadIdx.x;
    if (i >= NN) return;
    d_dis[i] = rsqrtf(d_degf[i]);        // degf >= 1 always
}

// Scatter edges into CSR slots with final coefficient fused:
// slot = {src, dis[src]*w}. One 8B store per edge (single random sector).
__global__ void k_build(const int* __restrict__ ei, const float* __restrict__ w) {
    int e = blockIdx.x * blockDim.x + threadIdx.x;
    if (e >= EE) return;
    int r = ei[e];
    int c = ei[EE + e];
    float n = w[e] * d_dis[r];
    int pos = atomicAdd(&d_fill[c], 1);
    d_edge[pos] = make_int2(r, __float_as_int(n));
}

// Layer 1: T = x @ W1 (padded cols zeroed)
__global__ void k_mm1(const float* __restrict__ x, const float* __restrict__ W1) {
    __shared__ float sW[FIN * HH];
    for (int t = threadIdx.x; t < FIN * HH; t += blockDim.x) sW[t] = W1[t];
    __syncthreads();
    int i = blockIdx.x * blockDim.x + threadIdx.x;
    if (i >= NN) return;
    float xv[FIN];
#pragma unroll
    for (int k = 0; k < FIN; k++) xv[k] = x[i * FIN + k];
#pragma unroll
    for (int j = 0; j < HH; j++) {
        float t = 0.0f;
#pragma unroll
        for (int k = 0; k < FIN; k++) t += xv[k] * sW[k * HH + j];
        d_T[i * HP + j] = t;
    }
    d_T[i * HP + 30] = 0.0f;
    d_T[i * HP + 31] = 0.0f;
}

// Layers 2/3: h = relu(A + b_prev); T = h @ W
__global__ void k_mm23(const float* __restrict__ W, const float* __restrict__ bprev) {
    __shared__ float sW[HH * HH];
    __shared__ float sb[HH];
    for (int t = threadIdx.x; t < HH * HH; t += blockDim.x) sW[t] = W[t];
    if (threadIdx.x < HH) sb[threadIdx.x] = bprev[threadIdx.x];
    __syncthreads();
    int i = blockIdx.x * blockDim.x + threadIdx.x;
    if (i >= NN) return;
    float h[HH];
#pragma unroll
    for (int k = 0; k < HH; k++) h[k] = fmaxf(d_A[i * HP + k] + sb[k], 0.0f);
#pragma unroll
    for (int j = 0; j < HH; j++) {
        float t = 0.0f;
#pragma unroll
        for (int k = 0; k < HH; k++) t += h[k] * sW[k * HH + j];
        d_T[i * HP + j] = t;
    }
    d_T[i * HP + 30] = 0.0f;
    d_T[i * HP + 31] = 0.0f;
}

// Gather: one warp per node, lane = feature column.
// A[i] = dis[i] * ( sum_j n_j*T[src_j] + dis[i]*T[i] ). 4-way ILP; no atomics.
__global__ void k_gather() {
    int warp = (blockIdx.x * blockDim.x + threadIdx.x) >> 5;
    if (warp >= NN) return;
    int lane = threadIdx.x & 31;
    int s = d_off[warp], e = d_off[warp + 1];
    float a0 = 0.0f, a1 = 0.0f, a2 = 0.0f, a3 = 0.0f;
    int j = s;
    for (; j + 3 < e; j += 4) {
        int2 m0 = d_edge[j];
        int2 m1 = d_edge[j + 1];
        int2 m2 = d_edge[j + 2];
        int2 m3 = d_edge[j + 3];
        a0 += __int_as_float(m0.y) * d_T[m0.x * HP + lane];
        a1 += __int_as_float(m1.y) * d_T[m1.x * HP + lane];
        a2 += __int_as_float(m2.y) * d_T[m2.x * HP + lane];
        a3 += __int_as_float(m3.y) * d_T[m3.x * HP + lane];
    }
    for (; j < e; j++) {
        int2 m = d_edge[j];
        a0 += __int_as_float(m.y) * d_T[m.x * HP + lane];
    }
    float di = d_dis[warp];
    d_A[warp * HP + lane] = di * ((a0 + a1) + (a2 + a3) + di * d_T[warp * HP + lane]);
}

// Graph segment boundaries: batch is sorted int32; lower_bound(g).
__global__ void k_bounds(const int* __restrict__ batch) {
    int g = threadIdx.x;                 // 0..511
    int lo = 0, hi = NN;
    while (lo < hi) {
        int mid = (lo + hi) >> 1;
        if (batch[mid] < g) lo = mid + 1; else hi = mid;
    }
    d_seglo[g] = lo;
    if (g == 0) d_seglo[GG] = NN;
}

// Pool: block per graph (8 warps), lane = feature; max over relu(A + b3).
__global__ void k_pool(const float* __restrict__ b3) {
    __shared__ float sm[8][32];
    int g = blockIdx.x;
    int lo = d_seglo[g], hi = d_seglo[g + 1];
    int w = threadIdx.x >> 5, lane = threadIdx.x & 31;
    float bb = (lane < HH) ? b3[lane] : 0.0f;
    float mx = 0.0f;
    for (int i = lo + w; i < hi; i += 8)
        mx = fmaxf(mx, d_A[i * HP + lane] + bb);
    sm[w][lane] = mx;
    __syncthreads();
    if (threadIdx.x < 32) {
        float m = sm[0][lane];
#pragma unroll
        for (int ww = 1; ww < 8; ww++) m = fmaxf(m, sm[ww][lane]);
        d_pooled[g * HP + lane] = m;
    }
}

// Final MLP: out[g] = relu(p @ LW1 + Lb1) @ LW2 + Lb2
__global__ void k_mlp(const float* __restrict__ LW1, const float* __restrict__ Lb1,
                      const float* __restrict__ LW2, const float* __restrict__ Lb2,
                      float* __restrict__ out) {
    __shared__ float sW1[HH * 10];
    __shared__ float sb1[10];
    __shared__ float sW2[10 * 2];
    __shared__ float sb2[2];
    for (int t = threadIdx.x; t < HH * 10; t += blockDim.x) sW1[t] = LW1[t];
    if (threadIdx.x < 10) sb1[threadIdx.x] = Lb1[threadIdx.x];
    if (threadIdx.x < 20) sW2[threadIdx.x] = LW2[threadIdx.x];
    if (threadIdx.x < 2)  sb2[threadIdx.x] = Lb2[threadIdx.x];
    __syncthreads();
    int g = threadIdx.x;
    if (g >= GG) return;
    float p[HH];
#pragma unroll
    for (int k = 0; k < HH; k++) p[k] = d_pooled[g * HP + k];
    float z[10];
#pragma unroll
    for (int j = 0; j < 10; j++) {
        float t = sb1[j];
#pragma unroll
        for (int k = 0; k < HH; k++) t += p[k] * sW1[k * 10 + j];
        z[j] = fmaxf(t, 0.0f);
    }
#pragma unroll
    for (int o = 0; o < 2; o++) {
        float t = sb2[o];
#pragma unroll
        for (int j = 0; j < 10; j++) t += z[j] * sW2[j * 2 + o];
        out[g * 2 + o] = t;
    }
}

extern "C" void kernel_launch(void* const* d_in, const int* in_sizes, int n_in,
                              void* d_out, int out_size) {
    const float* x     = (const float*)d_in[0];
    const int*   ei    = (const int*)d_in[1];    // int32 (JAX x64 disabled)
    const int*   batch = (const int*)d_in[2];    // int32
    const float* w     = (const float*)d_in[3];
    const float* W1    = (const float*)d_in[4];
    const float* b1    = (const float*)d_in[5];
    const float* W2    = (const float*)d_in[6];
    const float* b2    = (const float*)d_in[7];
    const float* W3    = (const float*)d_in[8];
    const float* b3    = (const float*)d_in[9];
    const float* LW1   = (const float*)d_in[10];
    const float* Lb1   = (const float*)d_in[11];
    const float* LW2   = (const float*)d_in[12];
    const float* Lb2   = (const float*)d_in[13];
    float* out = (float*)d_out;

    const int TB = 256;
    const int gN = (NN + TB - 1) / TB;
    const int gE = (EE + TB - 1) / TB;
    const int gW = (NN * 32) / TB;       // one warp per node (exact multiple)

    k_init<<<gN, TB>>>();
    k_cnt<<<gE, TB>>>(ei, w);
    k_scan<<<1, 512>>>();
    k_dis<<<gN, TB>>>();
    k_build<<<gE, TB>>>(ei, w);

    k_mm1<<<gN, TB>>>(x, W1);
    k_gather<<<gW, TB>>>();

    k_mm23<<<gN, TB>>>(W2, b1);
    k_gather<<<gW, TB>>>();

    k_mm23<<<gN, TB>>>(W3, b2);
    k_gather<<<gW, TB>>>();

    k_bounds<<<1, 512>>>(batch);
    k_pool<<<GG, TB>>>(b3);
    k_mlp<<<1, 512>>>(LW1, Lb1, LW2, Lb2, out);
}

// round 12
// speedup vs baseline: 1.0284x; 1.0133x over previous
#include <cuda_runtime.h>
#include <cuda_fp16.h>

#define NN 100000
#define EE 3200000
#define GG 512
#define HH 30
#define HP 32          // padded row stride: 32 halves = 64 bytes
#define FIN 10

// ---- static scratch (no runtime allocation) ----
__device__ __align__(128) __half d_T[NN * HP];  // h @ W, fp16 (64B rows)
__device__ __align__(128) float  d_A[NN * HP];  // aggregated output, fp32
__device__ float d_degf[NN];         // weighted degree accumulator
__device__ float d_dis[NN];          // 1/sqrt(deg)
__device__ int   d_cnt[NN];          // in-degree count
__device__ int   d_off[NN + 1];      // CSR offsets (by destination)
__device__ int   d_fill[NN];         // position-claim counters
__device__ int2  d_edge[EE];         // CSR slot: {src, float_bits(dis[src]*w)}
__device__ int   d_seglo[GG + 1];    // graph segment bounds in sorted batch
__device__ float d_pooled[GG * HP];  // pooled features

__global__ void k_init() {
    int i = blockIdx.x * blockDim.x + threadIdx.x;
    if (i < NN) { d_cnt[i] = 0; d_degf[i] = 1.0f; }  // self-loop weight 1
}

// Count in-degree AND accumulate weighted degree (edge_index is int32).
__global__ void k_cnt(const int* __restrict__ ei, const float* __restrict__ w) {
    int e = blockIdx.x * blockDim.x + threadIdx.x;
    if (e >= EE) return;
    int c = ei[EE + e];                  // destination
    atomicAdd(&d_cnt[c], 1);
    atomicAdd(&d_degf[c], w[e]);
}

// Single-block exclusive scan of d_cnt -> d_off / d_fill. 512 threads, chunk 196.
__global__ void k_scan() {
    __shared__ int s[512];
    const int CH = 196;                  // 512*196 = 100352 >= NN
    int t = threadIdx.x;
    int base = t * CH;
    int sum = 0;
    for (int k = 0; k < CH; k++) {
        int i = base + k;
        if (i < NN) sum += d_cnt[i];
    }
    s[t] = sum;
    __syncthreads();
    for (int off = 1; off < 512; off <<= 1) {
        int v = (t >= off) ? s[t - off] : 0;
        __syncthreads();
        s[t] += v;
        __syncthreads();
    }
    int run = s[t] - sum;                // exclusive prefix
    for (int k = 0; k < CH; k++) {
        int i = base + k;
        if (i < NN) {
            d_off[i] = run;
            d_fill[i] = run;
            run += d_cnt[i];
        }
    }
    if (t == 511) d_off[NN] = run;       // == EE
}

__global__ void k_dis() {
    int i = blockIdx.x * blockDim.x + threadIdx.x;
    if (i >= NN) return;
    d_dis[i] = rsqrtf(d_degf[i]);        // degf >= 1 always
}

// Scatter edges into CSR slots: slot = {src, dis[src]*w}. One 8B store/edge.
__global__ void k_build(const int* __restrict__ ei, const float* __restrict__ w) {
    int e = blockIdx.x * blockDim.x + threadIdx.x;
    if (e >= EE) return;
    int r = ei[e];
    int c = ei[EE + e];
    float n = w[e] * d_dis[r];
    int pos = atomicAdd(&d_fill[c], 1);
    d_edge[pos] = make_int2(r, __float_as_int(n));
}

// Layer 1: T = x @ W1 (fp16 store, padded cols zeroed)
__global__ void k_mm1(const float* __restrict__ x, const float* __restrict__ W1) {
    __shared__ float sW[FIN * HH];
    for (int t = threadIdx.x; t < FIN * HH; t += blockDim.x) sW[t] = W1[t];
    __syncthreads();
    int i = blockIdx.x * blockDim.x + threadIdx.x;
    if (i >= NN) return;
    float xv[FIN];
#pragma unroll
    for (int k = 0; k < FIN; k++) xv[k] = x[i * FIN + k];
#pragma unroll
    for (int j = 0; j < HH; j++) {
        float t = 0.0f;
#pragma unroll
        for (int k = 0; k < FIN; k++) t += xv[k] * sW[k * HH + j];
        d_T[i * HP + j] = __float2half_rn(t);
    }
    d_T[i * HP + 30] = __float2half_rn(0.0f);
    d_T[i * HP + 31] = __float2half_rn(0.0f);
}

// Layers 2/3: h = relu(A + b_prev); T = h @ W (fp16 store)
__global__ void k_mm23(const float* __restrict__ W, const float* __restrict__ bprev) {
    __shared__ float sW[HH * HH];
    __shared__ float sb[HH];
    for (int t = threadIdx.x; t < HH * HH; t += blockDim.x) sW[t] = W[t];
    if (threadIdx.x < HH) sb[threadIdx.x] = bprev[threadIdx.x];
    __syncthreads();
    int i = blockIdx.x * blockDim.x + threadIdx.x;
    if (i >= NN) return;
    float h[HH];
#pragma unroll
    for (int k = 0; k < HH; k++) h[k] = fmaxf(d_A[i * HP + k] + sb[k], 0.0f);
#pragma unroll
    for (int j = 0; j < HH; j++) {
        float t = 0.0f;
#pragma unroll
        for (int k = 0; k < HH; k++) t += h[k] * sW[k * HH + j];
        d_T[i * HP + j] = __float2half_rn(t);
    }
    d_T[i * HP + 30] = __float2half_rn(0.0f);
    d_T[i * HP + 31] = __float2half_rn(0.0f);
}

// Gather: one warp per node, lane = feature column; T rows are 64B fp16.
// A[i] = dis[i] * ( sum_j n_j*T[src_j] + dis[i]*T[i] ). fp32 accumulate.
__global__ void k_gather() {
    int warp = (blockIdx.x * blockDim.x + threadIdx.x) >> 5;
    if (warp >= NN) return;
    int lane = threadIdx.x & 31;
    int s = d_off[warp], e = d_off[warp + 1];
    float a0 = 0.0f, a1 = 0.0f, a2 = 0.0f, a3 = 0.0f;
    int j = s;
    for (; j + 3 < e; j += 4) {
        int2 m0 = d_edge[j];
        int2 m1 = d_edge[j + 1];
        int2 m2 = d_edge[j + 2];
        int2 m3 = d_edge[j + 3];
        a0 += __int_as_float(m0.y) * __half2float(d_T[m0.x * HP + lane]);
        a1 += __int_as_float(m1.y) * __half2float(d_T[m1.x * HP + lane]);
        a2 += __int_as_float(m2.y) * __half2float(d_T[m2.x * HP + lane]);
        a3 += __int_as_float(m3.y) * __half2float(d_T[m3.x * HP + lane]);
    }
    for (; j < e; j++) {
        int2 m = d_edge[j];
        a0 += __int_as_float(m.y) * __half2float(d_T[m.x * HP + lane]);
    }
    float di = d_dis[warp];
    float self = __half2float(d_T[warp * HP + lane]);
    d_A[warp * HP + lane] = di * ((a0 + a1) + (a2 + a3) + di * self);
}

// Graph segment boundaries: batch is sorted int32; lower_bound(g).
__global__ void k_bounds(const int* __restrict__ batch) {
    int g = threadIdx.x;                 // 0..511
    int lo = 0, hi = NN;
    while (lo < hi) {
        int mid = (lo + hi) >> 1;
        if (batch[mid] < g) lo = mid + 1; else hi = mid;
    }
    d_seglo[g] = lo;
    if (g == 0) d_seglo[GG] = NN;
}

// Pool: block per graph (8 warps), lane = feature; max over relu(A + b3).
__global__ void k_pool(const float* __restrict__ b3) {
    __shared__ float sm[8][32];
    int g = blockIdx.x;
    int lo = d_seglo[g], hi = d_seglo[g + 1];
    int w = threadIdx.x >> 5, lane = threadIdx.x & 31;
    float bb = (lane < HH) ? b3[lane] : 0.0f;
    float mx = 0.0f;
    for (int i = lo + w; i < hi; i += 8)
        mx = fmaxf(mx, d_A[i * HP + lane] + bb);
    sm[w][lane] = mx;
    __syncthreads();
    if (threadIdx.x < 32) {
        float m = sm[0][lane];
#pragma unroll
        for (int ww = 1; ww < 8; ww++) m = fmaxf(m, sm[ww][lane]);
        d_pooled[g * HP + lane] = m;
    }
}

// Final MLP: out[g] = relu(p @ LW1 + Lb1) @ LW2 + Lb2
__global__ void k_mlp(const float* __restrict__ LW1, const float* __restrict__ Lb1,
                      const float* __restrict__ LW2, const float* __restrict__ Lb2,
                      float* __restrict__ out) {
    __shared__ float sW1[HH * 10];
    __shared__ float sb1[10];
    __shared__ float sW2[10 * 2];
    __shared__ float sb2[2];
    for (int t = threadIdx.x; t < HH * 10; t += blockDim.x) sW1[t] = LW1[t];
    if (threadIdx.x < 10) sb1[threadIdx.x] = Lb1[threadIdx.x];
    if (threadIdx.x < 20) sW2[threadIdx.x] = LW2[threadIdx.x];
    if (threadIdx.x < 2)  sb2[threadIdx.x] = Lb2[threadIdx.x];
    __syncthreads();
    int g = threadIdx.x;
    if (g >= GG) return;
    float p[HH];
#pragma unroll
    for (int k = 0; k < HH; k++) p[k] = d_pooled[g * HP + k];
    float z[10];
#pragma unroll
    for (int j = 0; j < 10; j++) {
        float t = sb1[j];
#pragma unroll
        for (int k = 0; k < HH; k++) t += p[k] * sW1[k * 10 + j];
        z[j] = fmaxf(t, 0.0f);
    }
#pragma unroll
    for (int o = 0; o < 2; o++) {
        float t = sb2[o];
#pragma unroll
        for (int j = 0; j < 10; j++) t += z[j] * sW2[j * 2 + o];
        out[g * 2 + o] = t;
    }
}

extern "C" void kernel_launch(void* const* d_in, const int* in_sizes, int n_in,
                              void* d_out, int out_size) {
    const float* x     = (const float*)d_in[0];
    const int*   ei    = (const int*)d_in[1];    // int32 (JAX x64 disabled)
    const int*   batch = (const int*)d_in[2];    // int32
    const float* w     = (const float*)d_in[3];
    const float* W1    = (const float*)d_in[4];
    const float* b1    = (const float*)d_in[5];
    const float* W2    = (const float*)d_in[6];
    const float* b2    = (const float*)d_in[7];
    const float* W3    = (const float*)d_in[8];
    const float* b3    = (const float*)d_in[9];
    const float* LW1   = (const float*)d_in[10];
    const float* Lb1   = (const float*)d_in[11];
    const float* LW2   = (const float*)d_in[12];
    const float* Lb2   = (const float*)d_in[13];
    float* out = (float*)d_out;

    const int TB = 256;
    const int gN = (NN + TB - 1) / TB;
    const int gE = (EE + TB - 1) / TB;
    const int gW = (NN * 32) / TB;       // one warp per node (exact multiple)

    k_init<<<gN, TB>>>();
    k_cnt<<<gE, TB>>>(ei, w);
    k_scan<<<1, 512>>>();
    k_dis<<<gN, TB>>>();
    k_build<<<gE, TB>>>(ei, w);

    k_mm1<<<gN, TB>>>(x, W1);
    k_gather<<<gW, TB>>>();

    k_mm23<<<gN, TB>>>(W2, b1);
    k_gather<<<gW, TB>>>();

    k_mm23<<<gN, TB>>>(W3, b2);
    k_gather<<<gW, TB>>>();

    k_bounds<<<1, 512>>>(batch);
    k_pool<<<GG, TB>>>(b3);
    k_mlp<<<1, 512>>>(LW1, Lb1, LW2, Lb2, out);
}